// round 4
// baseline (speedup 1.0000x reference)
#include <cuda_runtime.h>
#include <cstdint>

#define D   128
#define NN  512
#define BB  4
#define RPB 8     // rows per block
#define NBLK 256u

// Scratch (device globals — no allocation allowed)
__device__ float g_part[28 * D];     // 7 jobs x 4 f-chunks x 128 outputs
__device__ float g_r[BB * NN * 4];   // per row: li0, li1, lj0, lj1

// Grid-barrier state (monotonic across graph replays — no reset needed)
__device__ unsigned g_bar_count[2] = {0u, 0u};
__device__ unsigned g_bar_gen[2]   = {0u, 0u};

__device__ __forceinline__ void grid_sync(int i) {
    __syncthreads();
    if (threadIdx.x == 0) {
        __threadfence();                       // release: make block's writes visible
        volatile unsigned* genp = &g_bar_gen[i];
        unsigned gen = *genp;
        unsigned ticket = atomicAdd(&g_bar_count[i], 1u);
        if ((ticket % NBLK) == NBLK - 1u) {
            atomicAdd(&g_bar_gen[i], 1u);      // last arriver releases everyone
        } else {
            while (*genp == gen) { }           // spin on L2 (all blocks resident)
        }
        __threadfence();                       // acquire
    }
    __syncthreads();
}

// smem layout (floats): W2 16384 | h 1024 | Hf 1024 | Wc 512 | p 8
#define SMEM_FLOATS (16384 + 1024 + 1024 + 512 + 8)

__global__ void fused_kernel(const int*   __restrict__ adj,
                             const int*   __restrict__ t,
                             const float* __restrict__ TE,
                             const float* __restrict__ nc,
                             const float* __restrict__ EE,
                             const float* __restrict__ W1,
                             const float* __restrict__ b1,
                             const float* __restrict__ W2,
                             const float* __restrict__ b2,
                             const float* __restrict__ Wc,
                             const float* __restrict__ bc,
                             float*       __restrict__ out)
{
    extern __shared__ float smem[];
    float* W2s = smem;                       // [d*128 + e]
    float* h_s = smem + 16384;               // [d*8 + r]
    float* Hfs = smem + 16384 + 1024;        // [r*128 + e]
    float* Wcs = smem + 16384 + 2048;        // [e*4 + c]
    float* p_s = smem + 16384 + 2048 + 512;  // [8]

    const int tid   = threadIdx.x;
    const int bid   = blockIdx.x;
    const int b     = bid >> 6;
    const int i0    = (bid & 63) * RPB;
    const int grow0 = b * NN + i0;

    const int e    = tid & 127;
    const int g    = tid >> 7;       // 0/1: 4-row group
    const int warp = tid >> 5;       // 0..7
    const int lane = tid & 31;

    // ---------------- Phase A ----------------
    // Setup partial (blocks 0..27, lower 128 threads): one f-chunk of one
    // coefficient job, folded against a W1 slice. Fully unrolled, MLP=32.
    if (bid < 28 && tid < 128) {
        const int j  = bid >> 2;     // 0..6
        const int f0 = (bid & 3) * 32;
        const int blk = (j <= 1) ? 0 : (j == 2 ? 1 : 2);
        const float* W = W1 + ((size_t)blk * D + f0) * D + tid;
        const float* cp;
        float csub = 0.f;
        if (j == 0)      { cp = EE + f0;      csub = 1.f; }   // E1 - E0
        else if (j == 1) { cp = EE + f0; }
        else if (j == 2) { cp = nc + f0; }
        else             { cp = TE + (size_t)t[j - 3] * D + f0; }
        float acc = 0.f;
#pragma unroll
        for (int f = 0; f < 32; f++) {
            float cv = (csub != 0.f) ? (EE[D + f0 + f] - cp[f]) : cp[f];
            acc = fmaf(cv, W[(size_t)f * D], acc);
        }
        g_part[bid * D + tid] = acc;
    }

    // All blocks: stage W2 into smem (coalesced float4)
    {
        const float4* W2_4 = (const float4*)W2;
        float4* W2s_4 = (float4*)W2s;
#pragma unroll
        for (int k = 0; k < 16; k++) W2s_4[tid + k * 256] = W2_4[tid + k * 256];
    }
    // Stage Wc columns
    if (g == 0) {
        float4 wc = make_float4(Wc[e * 2 + 0], Wc[e * 2 + 1],
                                Wc[(D + e) * 2 + 0], Wc[(D + e) * 2 + 1]);
        *(float4*)(Wcs + e * 4) = wc;
    }
    // p: warp w reduces adjacency row w (512 ints = 128 int4)
    {
        const int4* a4 = (const int4*)adj + (size_t)grow0 * (NN / 4);
        int s = 0;
#pragma unroll
        for (int k = 0; k < 4; k++) {
            int4 v = a4[warp * 128 + k * 32 + lane];
            s += v.x + v.y + v.z + v.w;
        }
#pragma unroll
        for (int o = 16; o; o >>= 1) s += __shfl_xor_sync(0xffffffffu, s, o);
        if (lane == 0) p_s[warp] = (float)s * (1.0f / 512.0f);
    }

    grid_sync(0);   // g_part complete everywhere; p_s/W2s/Wcs covered by its syncthreads

    // ---------------- Phase B ----------------
    // Finalize v1/base from partials (L2-hot, 16 independent loads)
    float v1e   = 0.f;
    float basee = b1[e];
#pragma unroll
    for (int c = 0; c < 4; c++) {
        v1e   += g_part[(0 * 4 + c) * D + e];
        basee += g_part[(1 * 4 + c) * D + e]
               + g_part[(2 * 4 + c) * D + e]
               + g_part[((3 + b) * 4 + c) * D + e];
    }
    const float b2e = b2[e];

    // h for this thread's 4 rows at element e
    {
        float4 pr = *(const float4*)(p_s + 4 * g);
        float h0 = fmaxf(fmaf(pr.x, v1e, basee), 0.f);
        float h1 = fmaxf(fmaf(pr.y, v1e, basee), 0.f);
        float h2 = fmaxf(fmaf(pr.z, v1e, basee), 0.f);
        float h3 = fmaxf(fmaf(pr.w, v1e, basee), 0.f);
        *(float4*)(h_s + e * 8 + 4 * g) = make_float4(h0, h1, h2, h3);
    }
    __syncthreads();

    // Matvec: Hf[r][e] = relu(sum_d h[r][d] * W2[d][e] + b2[e]), f32x2 pairs
    unsigned long long acc0, acc1;
    {
        unsigned int ub = __float_as_uint(b2e);
        asm("mov.b64 %0, {%1, %1};" : "=l"(acc0) : "r"(ub));
        acc1 = acc0;
    }
#pragma unroll 8
    for (int d = 0; d < D; d++) {
        float w = W2s[d * D + e];
        ulonglong2 hh = *(const ulonglong2*)(h_s + d * 8 + 4 * g);  // warp-uniform -> broadcast
        unsigned long long w2;
        asm("mov.b64 %0, {%1, %1};" : "=l"(w2) : "r"(__float_as_uint(w)));
        asm("fma.rn.f32x2 %0, %1, %2, %0;" : "+l"(acc0) : "l"(w2), "l"(hh.x));
        asm("fma.rn.f32x2 %0, %1, %2, %0;" : "+l"(acc1) : "l"(w2), "l"(hh.y));
    }
    {
        float2 f0 = *(float2*)&acc0;
        float2 f1 = *(float2*)&acc1;
        Hfs[(4 * g + 0) * D + e] = fmaxf(f0.x, 0.f);
        Hfs[(4 * g + 1) * D + e] = fmaxf(f0.y, 0.f);
        Hfs[(4 * g + 2) * D + e] = fmaxf(f1.x, 0.f);
        Hfs[(4 * g + 3) * D + e] = fmaxf(f1.y, 0.f);
    }
    __syncthreads();

    // Reduction: warp w handles row w, 4 dot products over e
    {
        int r = warp;
        float s0 = 0.f, s1 = 0.f, s2 = 0.f, s3 = 0.f;
#pragma unroll
        for (int k = 0; k < 4; k++) {
            int ee = lane + 32 * k;
            float hv = Hfs[r * D + ee];
            float4 wc = *(const float4*)(Wcs + ee * 4);
            s0 = fmaf(hv, wc.x, s0);
            s1 = fmaf(hv, wc.y, s1);
            s2 = fmaf(hv, wc.z, s2);
            s3 = fmaf(hv, wc.w, s3);
        }
#pragma unroll
        for (int o = 16; o; o >>= 1) {
            s0 += __shfl_xor_sync(0xffffffffu, s0, o);
            s1 += __shfl_xor_sync(0xffffffffu, s1, o);
            s2 += __shfl_xor_sync(0xffffffffu, s2, o);
            s3 += __shfl_xor_sync(0xffffffffu, s3, o);
        }
        if (lane == 0)
            *(float4*)(g_r + (size_t)(grow0 + r) * 4) = make_float4(s0, s1, s2, s3);
    }

    grid_sync(1);   // all g_r visible

    // ---------------- Phase C: expand (8 MB stream write) ----------------
    float2* lj_s = (float2*)W2s;   // reuse W2 smem (dead after matvec)
    const float bc0 = bc[0], bc1 = bc[1];
#pragma unroll
    for (int k = 0; k < 2; k++) {
        int j = tid + k * 256;
        float2 lj = *(const float2*)(g_r + (size_t)(b * NN + j) * 4 + 2);
        lj_s[j] = make_float2(lj.x + bc0, lj.y + bc1);
    }
    __syncthreads();

    float4* out4 = (float4*)out;
    const float4 a = *(const float4*)(lj_s + 2 * tid);  // (ljx0,ljy0,ljx1,ljy1)
#pragma unroll
    for (int r = 0; r < RPB; r++) {
        int row = b * NN + i0 + r;
        float2 li = *(const float2*)(g_r + (size_t)row * 4);
        out4[(size_t)row * 256 + tid] =
            make_float4(li.x + a.x, li.y + a.y, li.x + a.z, li.y + a.w);
    }
}

// ---------------------------------------------------------------------------
extern "C" void kernel_launch(void* const* d_in, const int* in_sizes, int n_in,
                              void* d_out, int out_size)
{
    const int*   adj = (const int*)d_in[0];
    const int*   t   = (const int*)d_in[1];
    const float* TE  = (const float*)d_in[2];
    const float* nc  = (const float*)d_in[3];
    const float* EE  = (const float*)d_in[4];
    const float* W1  = (const float*)d_in[5];
    const float* b1  = (const float*)d_in[6];
    const float* W2  = (const float*)d_in[7];
    const float* b2  = (const float*)d_in[8];
    const float* Wc  = (const float*)d_in[9];
    const float* bc  = (const float*)d_in[10];
    float* out = (float*)d_out;

    (void)in_sizes; (void)n_in; (void)out_size;

    const int smem_b = SMEM_FLOATS * sizeof(float);
    cudaFuncSetAttribute(fused_kernel, cudaFuncAttributeMaxDynamicSharedMemorySize, smem_b);

    fused_kernel<<<NBLK, 256, smem_b>>>(adj, t, TE, nc, EE, W1, b1, W2, b2, Wc, bc, out);
}

// round 5
// speedup vs baseline: 1.2447x; 1.2447x over previous
#include <cuda_runtime.h>
#include <cstdint>

#define D   128
#define NN  512
#define BB  4
#define RPB 8   // rows per block in row_kernel / expand_kernel

// Scratch (device globals — no allocation allowed)
__device__ float g_part[56 * D];     // 7 jobs x 8 f-chunks x 128 outputs
__device__ float g_r[BB * NN * 4];   // per row: li0, li1, lj0, lj1

// ---------------------------------------------------------------------------
// Kernel S: parallel fold of W1 against the 7 coefficient vectors.
//   job 0: (E1-E0) . W1[0:128]       -> v1
//   job 1:  E0     . W1[0:128]       -> base
//   job 2:  nc     . W1[128:256]     -> base
//   job 3..6: TE[t[b]] . W1[256:384] -> base (per batch)
// Grid 56 blocks = (j, f-chunk of 16), 128 threads (thread = output dim e).
// ---------------------------------------------------------------------------
__global__ void setup_partial(const int* __restrict__ t,
                              const float* __restrict__ TE,
                              const float* __restrict__ nc,
                              const float* __restrict__ EE,
                              const float* __restrict__ W1)
{
    __shared__ float s_coef[16];
    const int j  = blockIdx.x >> 3;   // 0..6
    const int c  = blockIdx.x & 7;    // f-chunk
    const int e  = threadIdx.x;       // 0..127
    const int f0 = c * 16;

    if (e < 16) {
        int f = f0 + e;
        float v;
        if (j == 0)      v = EE[D + f] - EE[f];
        else if (j == 1) v = EE[f];
        else if (j == 2) v = nc[f];
        else             v = TE[(size_t)t[j - 3] * D + f];
        s_coef[e] = v;
    }
    __syncthreads();

    const int blk = (j <= 1) ? 0 : (j == 2 ? 1 : 2);
    const float* W = W1 + ((size_t)blk * D + f0) * D + e;
    float acc = 0.f;
#pragma unroll
    for (int f = 0; f < 16; f++)
        acc = fmaf(s_coef[f], W[(size_t)f * D], acc);
    g_part[blockIdx.x * D + e] = acc;
    // implicit PDL trigger at kernel completion (full memory flush)
}

// ---------------------------------------------------------------------------
// Kernel B (PDL secondary): stages W2/Wc and reduces adj rows BEFORE the
// grid-dependency sync, so all of setup_partial hides under this prologue.
// ---------------------------------------------------------------------------
#define SMEM_B_FLOATS (16384 + 1024 + 1024 + 512 + 8)

__global__ void row_kernel(const int* __restrict__ adj,
                           const float* __restrict__ W2,
                           const float* __restrict__ b1,
                           const float* __restrict__ b2,
                           const float* __restrict__ Wc)
{
    extern __shared__ float smem[];
    float* W2s = smem;                       // [d*128 + e]
    float* h_s = smem + 16384;               // [d*8 + r]
    float* Hfs = smem + 16384 + 1024;        // [r*128 + e]
    float* Wcs = smem + 16384 + 2048;        // [e*4 + c]
    float* p_s = smem + 16384 + 2048 + 512;  // [8]

    const int tid   = threadIdx.x;
    const int b     = blockIdx.x >> 6;
    const int i0    = (blockIdx.x & 63) * RPB;
    const int grow0 = b * NN + i0;

    const int e    = tid & 127;
    const int g    = tid >> 7;       // 0/1: which 4-row group
    const int warp = tid >> 5;       // 0..7
    const int lane = tid & 31;

    // ---- pre-sync work (independent of setup_partial) ----
    {
        const float4* W2_4 = (const float4*)W2;
        float4* W2s_4 = (float4*)W2s;
#pragma unroll
        for (int k = 0; k < 16; k++) W2s_4[tid + k * 256] = W2_4[tid + k * 256];
    }
    if (g == 0) {
        float4 wc = make_float4(Wc[e * 2 + 0], Wc[e * 2 + 1],
                                Wc[(D + e) * 2 + 0], Wc[(D + e) * 2 + 1]);
        *(float4*)(Wcs + e * 4) = wc;
    }
    const float b1e = b1[e];
    const float b2e = b2[e];

    // p: warp w reduces adjacency row w (512 ints = 128 int4)
    {
        const int4* a4 = (const int4*)adj + (size_t)grow0 * (NN / 4);
        int s = 0;
#pragma unroll
        for (int k = 0; k < 4; k++) {
            int4 v = a4[warp * 128 + k * 32 + lane];
            s += v.x + v.y + v.z + v.w;
        }
#pragma unroll
        for (int o = 16; o; o >>= 1) s += __shfl_xor_sync(0xffffffffu, s, o);
        if (lane == 0) p_s[warp] = (float)s * (1.0f / 512.0f);
    }

    // ---- wait for setup_partial's g_part ----
    cudaGridDependencySynchronize();

    // Finalize v1/base from partials (32 independent L2-hot loads)
    float v1e   = 0.f;
    float basee = b1e;
#pragma unroll
    for (int c = 0; c < 8; c++) {
        v1e   += g_part[(0 * 8 + c) * D + e];
        basee += g_part[(1 * 8 + c) * D + e]
               + g_part[(2 * 8 + c) * D + e]
               + g_part[((3 + b) * 8 + c) * D + e];
    }
    __syncthreads();   // p_s ready

    // h for this thread's 4 rows at element e
    {
        float4 pr = *(const float4*)(p_s + 4 * g);
        float h0 = fmaxf(fmaf(pr.x, v1e, basee), 0.f);
        float h1 = fmaxf(fmaf(pr.y, v1e, basee), 0.f);
        float h2 = fmaxf(fmaf(pr.z, v1e, basee), 0.f);
        float h3 = fmaxf(fmaf(pr.w, v1e, basee), 0.f);
        *(float4*)(h_s + e * 8 + 4 * g) = make_float4(h0, h1, h2, h3);
    }
    __syncthreads();

    // Matvec: Hf[r][e] = relu(sum_d h[r][d] * W2[d][e] + b2[e]), f32x2 pairs
    unsigned long long acc0, acc1;
    {
        unsigned int ub = __float_as_uint(b2e);
        asm("mov.b64 %0, {%1, %1};" : "=l"(acc0) : "r"(ub));
        acc1 = acc0;
    }
#pragma unroll 8
    for (int d = 0; d < D; d++) {
        float w = W2s[d * D + e];
        ulonglong2 hh = *(const ulonglong2*)(h_s + d * 8 + 4 * g);
        unsigned long long w2;
        asm("mov.b64 %0, {%1, %1};" : "=l"(w2) : "r"(__float_as_uint(w)));
        asm("fma.rn.f32x2 %0, %1, %2, %0;" : "+l"(acc0) : "l"(w2), "l"(hh.x));
        asm("fma.rn.f32x2 %0, %1, %2, %0;" : "+l"(acc1) : "l"(w2), "l"(hh.y));
    }
    {
        float2 f0 = *(float2*)&acc0;
        float2 f1 = *(float2*)&acc1;
        Hfs[(4 * g + 0) * D + e] = fmaxf(f0.x, 0.f);
        Hfs[(4 * g + 1) * D + e] = fmaxf(f0.y, 0.f);
        Hfs[(4 * g + 2) * D + e] = fmaxf(f1.x, 0.f);
        Hfs[(4 * g + 3) * D + e] = fmaxf(f1.y, 0.f);
    }
    __syncthreads();

    // Reduction: warp w handles row w, 4 dot products over e
    {
        int r = warp;
        float s0 = 0.f, s1 = 0.f, s2 = 0.f, s3 = 0.f;
#pragma unroll
        for (int k = 0; k < 4; k++) {
            int ee = lane + 32 * k;
            float hv = Hfs[r * D + ee];
            float4 wc = *(const float4*)(Wcs + ee * 4);
            s0 = fmaf(hv, wc.x, s0);
            s1 = fmaf(hv, wc.y, s1);
            s2 = fmaf(hv, wc.z, s2);
            s3 = fmaf(hv, wc.w, s3);
        }
#pragma unroll
        for (int o = 16; o; o >>= 1) {
            s0 += __shfl_xor_sync(0xffffffffu, s0, o);
            s1 += __shfl_xor_sync(0xffffffffu, s1, o);
            s2 += __shfl_xor_sync(0xffffffffu, s2, o);
            s3 += __shfl_xor_sync(0xffffffffu, s3, o);
        }
        if (lane == 0)
            *(float4*)(g_r + (size_t)(grow0 + r) * 4) = make_float4(s0, s1, s2, s3);
    }
}

// ---------------------------------------------------------------------------
// Kernel C (PDL secondary): logits[b,i,j,:] = li[b,i] + lj[b,j] + bc.
// Pre-stages bc, waits on row_kernel, then streams the 8 MB write.
// ---------------------------------------------------------------------------
__global__ void expand_kernel(const float* __restrict__ bc,
                              float* __restrict__ out)
{
    __shared__ float2 lj_s[NN];
    const int tid = threadIdx.x;
    const int b   = blockIdx.x >> 6;
    const int i0  = (blockIdx.x & 63) * RPB;

    const float bc0 = bc[0], bc1 = bc[1];

    cudaGridDependencySynchronize();   // g_r complete

#pragma unroll
    for (int k = 0; k < 2; k++) {
        int j = tid + k * 256;
        float2 lj = *(const float2*)(g_r + (size_t)(b * NN + j) * 4 + 2);
        lj_s[j] = make_float2(lj.x + bc0, lj.y + bc1);
    }
    __syncthreads();

    float4* out4 = (float4*)out;
    const float4 a = *(const float4*)(lj_s + 2 * tid);  // (ljx0,ljy0,ljx1,ljy1)
#pragma unroll
    for (int r = 0; r < RPB; r++) {
        int row = b * NN + i0 + r;
        float2 li = *(const float2*)(g_r + (size_t)row * 4);
        out4[(size_t)row * 256 + tid] =
            make_float4(li.x + a.x, li.y + a.y, li.x + a.z, li.y + a.w);
    }
}

// ---------------------------------------------------------------------------
extern "C" void kernel_launch(void* const* d_in, const int* in_sizes, int n_in,
                              void* d_out, int out_size)
{
    const int*   adj = (const int*)d_in[0];
    const int*   t   = (const int*)d_in[1];
    const float* TE  = (const float*)d_in[2];
    const float* nc  = (const float*)d_in[3];
    const float* EE  = (const float*)d_in[4];
    const float* W1  = (const float*)d_in[5];
    const float* b1  = (const float*)d_in[6];
    const float* W2  = (const float*)d_in[7];
    const float* b2  = (const float*)d_in[8];
    const float* Wc  = (const float*)d_in[9];
    const float* bc  = (const float*)d_in[10];
    float* out = (float*)d_out;

    (void)in_sizes; (void)n_in; (void)out_size;

    const int smem_b = SMEM_B_FLOATS * sizeof(float);
    static int configured = 0;
    if (!configured) {
        cudaFuncSetAttribute(row_kernel, cudaFuncAttributeMaxDynamicSharedMemorySize, smem_b);
        configured = 1;
    }

    // Node 1: setup fold
    setup_partial<<<56, 128>>>(t, TE, nc, EE, W1);

    // Node 2: row kernel, programmatic dependency on setup
    cudaLaunchAttribute pdl[1];
    pdl[0].id = cudaLaunchAttributeProgrammaticStreamSerialization;
    pdl[0].val.programmaticStreamSerializationAllowed = 1;

    cudaLaunchConfig_t cfg = {};
    cfg.gridDim = dim3(256);
    cfg.blockDim = dim3(256);
    cfg.dynamicSmemBytes = smem_b;
    cfg.stream = 0;
    cfg.attrs = pdl;
    cfg.numAttrs = 1;
    cudaLaunchKernelEx(&cfg, row_kernel, adj, W2, b1, b2, Wc);

    // Node 3: expand, programmatic dependency on row_kernel
    cudaLaunchConfig_t cfg2 = {};
    cfg2.gridDim = dim3(256);
    cfg2.blockDim = dim3(256);
    cfg2.dynamicSmemBytes = 0;
    cfg2.stream = 0;
    cfg2.attrs = pdl;
    cfg2.numAttrs = 1;
    cudaLaunchKernelEx(&cfg2, expand_kernel, bc, out);
}

// round 6
// speedup vs baseline: 1.2635x; 1.0151x over previous
#include <cuda_runtime.h>
#include <cstdint>

#define D   128
#define NN  512
#define BB  4
#define RPB 8       // rows per block
#define NPROD 56u   // producer blocks (7 jobs x 8 f-chunks)

// Scratch (device globals — no allocation allowed)
__device__ float g_part[56 * D];     // 7 jobs x 8 f-chunks x 128 outputs
__device__ float g_r[BB * NN * 4];   // per row: li0, li1, lj0, lj1
__device__ unsigned g_ready = 0u;    // producer completion counter (reset in expand)

// smem: W2 16384 | h 1024 | Hf 1024 | Wc 512 | p 8
#define SMEM_B_FLOATS (16384 + 1024 + 1024 + 512 + 8)

// ---------------------------------------------------------------------------
// Kernel 1: fold (blocks 0..55) + per-row MLP for all 2048 rows.
// Producers write g_part then release via g_ready; consumers overlap their
// prologue (W2 staging, adj row-sums) with the fold, then spin (near-zero).
// ---------------------------------------------------------------------------
__global__ void __launch_bounds__(256, 2)
row_kernel(const int*   __restrict__ adj,
           const int*   __restrict__ t,
           const float* __restrict__ TE,
           const float* __restrict__ nc,
           const float* __restrict__ EE,
           const float* __restrict__ W1,
           const float* __restrict__ b1,
           const float* __restrict__ W2,
           const float* __restrict__ b2,
           const float* __restrict__ Wc)
{
    extern __shared__ float smem[];
    float* W2s = smem;                       // [d*128 + e]
    float* h_s = smem + 16384;               // [d*8 + r]
    float* Hfs = smem + 16384 + 1024;        // [r*128 + e]
    float* Wcs = smem + 16384 + 2048;        // [e*4 + c]
    float* p_s = smem + 16384 + 2048 + 512;  // [8]

    const int tid   = threadIdx.x;
    const int bid   = blockIdx.x;
    const int b     = bid >> 6;
    const int i0    = (bid & 63) * RPB;
    const int grow0 = b * NN + i0;

    const int e    = tid & 127;
    const int g    = tid >> 7;       // 0/1: 4-row group
    const int warp = tid >> 5;       // 0..7
    const int lane = tid & 31;

    // ---- producer role: W1 fold chunk (blocks 0..55) ----
    if (bid < (int)NPROD) {
        __shared__ float s_coef[16];
        const int j  = bid >> 3;     // 0..6
        const int f0 = (bid & 7) * 16;
        if (tid < 16) {
            int f = f0 + tid;
            float v;
            if (j == 0)      v = EE[D + f] - EE[f];
            else if (j == 1) v = EE[f];
            else if (j == 2) v = nc[f];
            else             v = TE[(size_t)t[j - 3] * D + f];
            s_coef[tid] = v;
        }
        __syncthreads();
        if (tid < 128) {
            const int blk = (j <= 1) ? 0 : (j == 2 ? 1 : 2);
            const float* W = W1 + ((size_t)blk * D + f0) * D + tid;
            float acc = 0.f;
#pragma unroll
            for (int f = 0; f < 16; f++)
                acc = fmaf(s_coef[f], W[(size_t)f * D], acc);
            g_part[bid * D + tid] = acc;
            __threadfence();         // release g_part before flag
        }
        __syncthreads();
        if (tid == 0) atomicAdd(&g_ready, 1u);
    }

    // ---- prologue (independent of fold) ----
    {
        const float4* W2_4 = (const float4*)W2;
        float4* W2s_4 = (float4*)W2s;
#pragma unroll
        for (int k = 0; k < 16; k++) W2s_4[tid + k * 256] = W2_4[tid + k * 256];
    }
    if (g == 0) {
        float4 wc = make_float4(Wc[e * 2 + 0], Wc[e * 2 + 1],
                                Wc[(D + e) * 2 + 0], Wc[(D + e) * 2 + 1]);
        *(float4*)(Wcs + e * 4) = wc;
    }
    const float b1e = b1[e];
    const float b2e = b2[e];

    // p: warp w reduces adjacency row w (512 ints = 128 int4, DRAM)
    {
        const int4* a4 = (const int4*)adj + (size_t)grow0 * (NN / 4);
        int s = 0;
#pragma unroll
        for (int k = 0; k < 4; k++) {
            int4 v = a4[warp * 128 + k * 32 + lane];
            s += v.x + v.y + v.z + v.w;
        }
#pragma unroll
        for (int o = 16; o; o >>= 1) s += __shfl_xor_sync(0xffffffffu, s, o);
        if (lane == 0) p_s[warp] = (float)s * (1.0f / 512.0f);
    }

    // ---- wait for all producer chunks (near-zero: fold << prologue) ----
    if (tid == 0) {
        while (*(volatile unsigned*)&g_ready < NPROD) __nanosleep(64);
        __threadfence();             // acquire
    }
    __syncthreads();

    // Finalize v1/base from partials (32 independent L2-hot loads)
    float v1e   = 0.f;
    float basee = b1e;
#pragma unroll
    for (int c = 0; c < 8; c++) {
        v1e   += g_part[(0 * 8 + c) * D + e];
        basee += g_part[(1 * 8 + c) * D + e]
               + g_part[(2 * 8 + c) * D + e]
               + g_part[((3 + b) * 8 + c) * D + e];
    }

    // h for this thread's 4 rows at element e
    {
        float4 pr = *(const float4*)(p_s + 4 * g);
        float h0 = fmaxf(fmaf(pr.x, v1e, basee), 0.f);
        float h1 = fmaxf(fmaf(pr.y, v1e, basee), 0.f);
        float h2 = fmaxf(fmaf(pr.z, v1e, basee), 0.f);
        float h3 = fmaxf(fmaf(pr.w, v1e, basee), 0.f);
        *(float4*)(h_s + e * 8 + 4 * g) = make_float4(h0, h1, h2, h3);
    }
    __syncthreads();

    // Matvec: Hf[r][e] = relu(sum_d h[r][d] * W2[d][e] + b2[e]), f32x2 pairs
    unsigned long long acc0, acc1;
    {
        unsigned int ub = __float_as_uint(b2e);
        asm("mov.b64 %0, {%1, %1};" : "=l"(acc0) : "r"(ub));
        acc1 = acc0;
    }
#pragma unroll 8
    for (int d = 0; d < D; d++) {
        float w = W2s[d * D + e];
        ulonglong2 hh = *(const ulonglong2*)(h_s + d * 8 + 4 * g);
        unsigned long long w2;
        asm("mov.b64 %0, {%1, %1};" : "=l"(w2) : "r"(__float_as_uint(w)));
        asm("fma.rn.f32x2 %0, %1, %2, %0;" : "+l"(acc0) : "l"(w2), "l"(hh.x));
        asm("fma.rn.f32x2 %0, %1, %2, %0;" : "+l"(acc1) : "l"(w2), "l"(hh.y));
    }
    {
        float2 f0 = *(float2*)&acc0;
        float2 f1 = *(float2*)&acc1;
        Hfs[(4 * g + 0) * D + e] = fmaxf(f0.x, 0.f);
        Hfs[(4 * g + 1) * D + e] = fmaxf(f0.y, 0.f);
        Hfs[(4 * g + 2) * D + e] = fmaxf(f1.x, 0.f);
        Hfs[(4 * g + 3) * D + e] = fmaxf(f1.y, 0.f);
    }
    __syncthreads();

    // Reduction: warp w handles row w, 4 dot products over e
    {
        int r = warp;
        float s0 = 0.f, s1 = 0.f, s2 = 0.f, s3 = 0.f;
#pragma unroll
        for (int k = 0; k < 4; k++) {
            int ee = lane + 32 * k;
            float hv = Hfs[r * D + ee];
            float4 wc = *(const float4*)(Wcs + ee * 4);
            s0 = fmaf(hv, wc.x, s0);
            s1 = fmaf(hv, wc.y, s1);
            s2 = fmaf(hv, wc.z, s2);
            s3 = fmaf(hv, wc.w, s3);
        }
#pragma unroll
        for (int o = 16; o; o >>= 1) {
            s0 += __shfl_xor_sync(0xffffffffu, s0, o);
            s1 += __shfl_xor_sync(0xffffffffu, s1, o);
            s2 += __shfl_xor_sync(0xffffffffu, s2, o);
            s3 += __shfl_xor_sync(0xffffffffu, s3, o);
        }
        if (lane == 0)
            *(float4*)(g_r + (size_t)(grow0 + r) * 4) = make_float4(s0, s1, s2, s3);
    }
}

// ---------------------------------------------------------------------------
// Kernel 2: logits[b,i,j,:] = li[b,i] + lj[b,j] + bc (8 MB stream write).
// Also resets g_ready for the next graph replay (k1/k2 strictly serialized).
// ---------------------------------------------------------------------------
__global__ void expand_kernel(const float* __restrict__ bc,
                              float* __restrict__ out)
{
    __shared__ float2 lj_s[NN];
    const int tid = threadIdx.x;
    const int b   = blockIdx.x >> 6;
    const int i0  = (blockIdx.x & 63) * RPB;

    if (blockIdx.x == 0 && tid == 0) g_ready = 0u;   // reset for next replay

    const float bc0 = bc[0], bc1 = bc[1];
#pragma unroll
    for (int k = 0; k < 2; k++) {
        int j = tid + k * 256;
        float2 lj = *(const float2*)(g_r + (size_t)(b * NN + j) * 4 + 2);
        lj_s[j] = make_float2(lj.x + bc0, lj.y + bc1);
    }
    __syncthreads();

    float4* out4 = (float4*)out;
    const float4 a = *(const float4*)(lj_s + 2 * tid);  // (ljx0,ljy0,ljx1,ljy1)
#pragma unroll
    for (int r = 0; r < RPB; r++) {
        int row = b * NN + i0 + r;
        float2 li = *(const float2*)(g_r + (size_t)row * 4);
        out4[(size_t)row * 256 + tid] =
            make_float4(li.x + a.x, li.y + a.y, li.x + a.z, li.y + a.w);
    }
}

// ---------------------------------------------------------------------------
extern "C" void kernel_launch(void* const* d_in, const int* in_sizes, int n_in,
                              void* d_out, int out_size)
{
    const int*   adj = (const int*)d_in[0];
    const int*   t   = (const int*)d_in[1];
    const float* TE  = (const float*)d_in[2];
    const float* nc  = (const float*)d_in[3];
    const float* EE  = (const float*)d_in[4];
    const float* W1  = (const float*)d_in[5];
    const float* b1  = (const float*)d_in[6];
    const float* W2  = (const float*)d_in[7];
    const float* b2  = (const float*)d_in[8];
    const float* Wc  = (const float*)d_in[9];
    const float* bc  = (const float*)d_in[10];
    float* out = (float*)d_out;

    (void)in_sizes; (void)n_in; (void)out_size;

    const int smem_b = SMEM_B_FLOATS * sizeof(float);
    cudaFuncSetAttribute(row_kernel, cudaFuncAttributeMaxDynamicSharedMemorySize, smem_b);

    row_kernel<<<256, 256, smem_b>>>(adj, t, TE, nc, EE, W1, b1, W2, b2, Wc);
    expand_kernel<<<256, 256>>>(bc, out);
}